// round 13
// baseline (speedup 1.0000x reference)
#include <cuda_runtime.h>
#include <cuda_bf16.h>
#include <math.h>
#include <stdint.h>

// Problem dims
#define NB   128
#define NT   20
#define VNUM 196
#define VDIM 512
#define NE   256
#define NH   512
#define NV   10000
#define G4   2048
#define TBR  2560   // NT*NB
#define NTILES 79   // ceil(NV/128)

// ---------------- helpers ----------------
__device__ __forceinline__ void mma16(float* c, const uint32_t* a, const uint32_t* b) {
    asm volatile("mma.sync.aligned.m16n8k16.row.col.f32.bf16.bf16.f32 "
                 "{%0,%1,%2,%3}, {%4,%5,%6,%7}, {%8,%9}, {%0,%1,%2,%3};"
                 : "+f"(c[0]), "+f"(c[1]), "+f"(c[2]), "+f"(c[3])
                 : "r"(a[0]), "r"(a[1]), "r"(a[2]), "r"(a[3]), "r"(b[0]), "r"(b[1]));
}
__device__ __forceinline__ uint32_t smem_u32(const void* p) {
    uint32_t a;
    asm("{ .reg .u64 t; cvta.to.shared.u64 t, %1; cvt.u32.u64 %0, t; }" : "=r"(a) : "l"(p));
    return a;
}
__device__ __forceinline__ void ldsm4(uint32_t* r, uint32_t addr) {
    asm volatile("ldmatrix.sync.aligned.m8n8.x4.shared.b16 {%0,%1,%2,%3}, [%4];"
                 : "=r"(r[0]), "=r"(r[1]), "=r"(r[2]), "=r"(r[3]) : "r"(addr));
}
__device__ __forceinline__ void cpa16(uint32_t saddr, const void* gaddr, uint32_t srcsz) {
    asm volatile("cp.async.cg.shared.global [%0], [%1], 16, %2;"
                 :: "r"(saddr), "l"(gaddr), "r"(srcsz));
}
#define CP_COMMIT() asm volatile("cp.async.commit_group;")
#define CP_WAIT1()  asm volatile("cp.async.wait_group 1;")
__device__ __forceinline__ float sigmoidf_(float x) { return 1.f / (1.f + __expf(-x)); }

// ---------------- scratch ----------------
__device__ __nv_bfloat16 d_emb_bf[TBR * NE];
__device__ __nv_bfloat16 d_wo_bf[(size_t)NV * NH];
__device__ __nv_bfloat16 d_wih_bf[G4 * NE];
__device__ __nv_bfloat16 d_hall_bf[(size_t)TBR * NH];
__device__ __nv_bfloat16 d_h0_bf[NB * NH];
__device__ __nv_bfloat16 d_logits_bf[(size_t)TBR * (NV + 16)];
__device__ float d_psum[(size_t)TBR * 80];     // [row][tile] partial exp sums (79 used)
__device__ float d_lse[TBR];
__device__ float d_attv[NB * VNUM];
__device__ float d_feat_sum[NB * VDIM];
__device__ float d_ctx[NB * VDIM];
__device__ float d_c0[NB * NH];
__device__ float d_gctx[NB * G4];
__device__ float d_gpre[(size_t)TBR * G4];
__device__ unsigned d_barCount;
__device__ unsigned d_barGen;

// ---------------- embedding gather -> bf16 ----------------
__global__ void k_gather(const int* __restrict__ cap, const float* __restrict__ et) {
    int r = blockIdx.x;                 // t*NB + b
    int t = r / NB, b = r % NB;
    int id = cap[b * NT + t];
    d_emb_bf[(size_t)r * NE + threadIdx.x] = __float2bfloat16(et[(size_t)id * NE + threadIdx.x]);
}

// ---------------- fp32 -> bf16 (4 elems/thread, packed 8B stores) ----------------
__global__ void k_cvtb(const float* __restrict__ src, int pitch, int cols,
                       __nv_bfloat16* __restrict__ dst, int n4) {
    int i = blockIdx.x * 256 + threadIdx.x;
    if (i >= n4) return;
    int e = i * 4;
    const float* s;
    if (pitch == cols) {
        s = src + e;
    } else {
        int r = e / cols, c = e % cols;
        s = src + (size_t)r * pitch + c;
    }
    float4 v = *(const float4*)s;
    __nv_bfloat162 p0 = __floats2bfloat162_rn(v.x, v.y);
    __nv_bfloat162 p1 = __floats2bfloat162_rn(v.z, v.w);
    uint2 pk;
    pk.x = *(uint32_t*)&p0;
    pk.y = *(uint32_t*)&p1;
    *(uint2*)(dst + e) = pk;
}

// ---------------- attention logits: one warp per (b, n) ----------------
__global__ void __launch_bounds__(256) k_att(const float* __restrict__ feat,
        const float* __restrict__ Wv, const float* __restrict__ bv) {
    int warp = threadIdx.x >> 5, lane = threadIdx.x & 31;
    int b = blockIdx.y;
    int n = blockIdx.x * 8 + warp;
    if (n >= VNUM) return;
    const float* fr = feat + ((size_t)b * VNUM + n) * VDIM;
    float acc = 0.f;
    #pragma unroll
    for (int k = lane; k < VDIM; k += 32) acc += fr[k] * Wv[k];
    #pragma unroll
    for (int o = 16; o; o >>= 1) acc += __shfl_xor_sync(0xffffffffu, acc, o);
    if (lane == 0) d_attv[b * VNUM + n] = acc + bv[0];
}

// ---------------- softmax(attv) -> feat_sum + ctx ----------------
__global__ void __launch_bounds__(256) k_ctx(const float* __restrict__ feat) {
    __shared__ float salpha[VNUM];
    __shared__ float red[256];
    __shared__ float sfs[256];
    __shared__ float sctx[256];
    int b = blockIdx.y, tid = threadIdx.x;
    int v0 = blockIdx.x * 128;
    float x = (tid < VNUM) ? d_attv[b * VNUM + tid] : -1e30f;
    red[tid] = x; __syncthreads();
    for (int s = 128; s; s >>= 1) { if (tid < s) red[tid] = fmaxf(red[tid], red[tid + s]); __syncthreads(); }
    float mx = red[0]; __syncthreads();
    float e = (tid < VNUM) ? __expf(x - mx) : 0.f;
    red[tid] = e; __syncthreads();
    for (int s = 128; s; s >>= 1) { if (tid < s) red[tid] += red[tid + s]; __syncthreads(); }
    float inv = 1.f / red[0];
    __syncthreads();
    if (tid < VNUM) salpha[tid] = e * inv;
    __syncthreads();

    int v = v0 + (tid & 127);
    int half = tid >> 7;
    int n0 = half * 98, n1 = n0 + 98;
    if (n1 > VNUM) n1 = VNUM;
    const float* fp = feat + (size_t)b * VNUM * VDIM + v;
    float fs = 0.f, c0 = 0.f, c1 = 0.f, c2 = 0.f, c3 = 0.f;
    int n = n0;
    for (; n + 4 <= n1; n += 4) {
        float x0 = fp[(size_t)n * VDIM];
        float x1 = fp[(size_t)(n + 1) * VDIM];
        float x2 = fp[(size_t)(n + 2) * VDIM];
        float x3 = fp[(size_t)(n + 3) * VDIM];
        fs += (x0 + x1) + (x2 + x3);
        c0 += salpha[n] * x0; c1 += salpha[n + 1] * x1;
        c2 += salpha[n + 2] * x2; c3 += salpha[n + 3] * x3;
    }
    for (; n < n1; n++) { float xx = fp[(size_t)n * VDIM]; fs += xx; c0 += salpha[n] * xx; }
    sfs[tid] = fs;
    sctx[tid] = (c0 + c1) + (c2 + c3);
    __syncthreads();
    if (half == 0) {
        d_feat_sum[b * VDIM + v] = sfs[tid] + sfs[tid + 128];
        d_ctx[b * VDIM + v] = sctx[tid] + sctx[tid + 128];
    }
}

// ---------------- fused init GEMMs: h0(bf16) | c0 | g_ctx (N=3072 concat) ----------------
__global__ void __launch_bounds__(256) k_init(
        const float* __restrict__ Wini_h, const float* __restrict__ Wini_c,
        const float* __restrict__ Wih,
        const float* __restrict__ bih, const float* __restrict__ bhh) {
    __shared__ float As[16][32];
    __shared__ float Bs[16][64];
    int ntile = blockIdx.x, mt = blockIdx.y;
    int seg, nloc0;
    const float* A;
    const float* B;
    int ldb;
    if (ntile < 8)       { seg = 0; nloc0 = ntile * 64;        A = d_feat_sum; B = Wini_h; ldb = VDIM; }
    else if (ntile < 16) { seg = 1; nloc0 = (ntile - 8) * 64;  A = d_feat_sum; B = Wini_c; ldb = VDIM; }
    else                 { seg = 2; nloc0 = (ntile - 16) * 64; A = d_ctx;      B = Wih;    ldb = VDIM + NE; }
    int tid = threadIdx.x;
    int tx = tid & 15, ty = tid >> 4;
    int m0 = mt * 32;
    float acc[2][4] = {{0.f, 0.f, 0.f, 0.f}, {0.f, 0.f, 0.f, 0.f}};
    for (int k0 = 0; k0 < VDIM; k0 += 16) {
        {
            int i = tid; int r = i >> 4, kk = i & 15;
            As[kk][r] = A[(size_t)(m0 + r) * VDIM + k0 + kk];
            i = tid + 256; r = i >> 4; kk = i & 15;
            As[kk][r] = A[(size_t)(m0 + r) * VDIM + k0 + kk];
        }
        #pragma unroll
        for (int j = 0; j < 4; j++) {
            int i = tid + j * 256; int r = i >> 4, kk = i & 15;
            Bs[kk][r] = B[(size_t)(nloc0 + r) * ldb + k0 + kk];
        }
        __syncthreads();
        #pragma unroll
        for (int kk = 0; kk < 16; kk++) {
            float a0 = As[kk][ty * 2], a1 = As[kk][ty * 2 + 1];
            float b0 = Bs[kk][tx * 4], b1 = Bs[kk][tx * 4 + 1];
            float b2 = Bs[kk][tx * 4 + 2], b3 = Bs[kk][tx * 4 + 3];
            acc[0][0] += a0 * b0; acc[0][1] += a0 * b1; acc[0][2] += a0 * b2; acc[0][3] += a0 * b3;
            acc[1][0] += a1 * b0; acc[1][1] += a1 * b1; acc[1][2] += a1 * b2; acc[1][3] += a1 * b3;
        }
        __syncthreads();
    }
    #pragma unroll
    for (int i = 0; i < 2; i++) {
        int m = m0 + ty * 2 + i;
        #pragma unroll
        for (int j = 0; j < 4; j++) {
            int n = nloc0 + tx * 4 + j;
            if (seg == 0) {
                d_h0_bf[(size_t)m * NH + n] = __float2bfloat16(acc[i][j] * (1.f / VNUM));
            } else if (seg == 1) {
                d_c0[(size_t)m * NH + n] = acc[i][j] * (1.f / VNUM);
            } else {
                d_gctx[(size_t)m * G4 + n] = acc[i][j] + bih[n] + bhh[n];
            }
        }
    }
}

// ======================= bf16 mma GEMM: BK=64, 3-stage cp.async, 2 CTAs/SM =========
// C fp32 (C != null) else Cb bf16 (+ optional per-tile exp row sums into psum).
#define BSTR64 72
#define TB_BUF (128 * BSTR64)
#define TB_STAGE_BYTES (2 * TB_BUF * 2)
#define TB_SMEM (3 * TB_STAGE_BYTES)

__global__ void __launch_bounds__(256, 2) tbmma(const __nv_bfloat16* __restrict__ A, int lda,
        const __nv_bfloat16* __restrict__ B, int ldb,
        float* __restrict__ C, __nv_bfloat16* __restrict__ Cb,
        int M, int N, int K,
        const float* __restrict__ bias, const float* __restrict__ addM, int addRowMod,
        float* __restrict__ psum) {
    extern __shared__ __align__(16) __nv_bfloat16 smb[];
    int tid = threadIdx.x, lane = tid & 31, wid = tid >> 5;
    int wm = wid & 1, wn = wid >> 1;
    int m0 = blockIdx.y * 128, n0 = blockIdx.x * 128;
    int gid = lane >> 2, tig = lane & 3;

    float acc[4][4][4];
    #pragma unroll
    for (int mi = 0; mi < 4; mi++)
        #pragma unroll
        for (int ni = 0; ni < 4; ni++)
            #pragma unroll
            for (int q = 0; q < 4; q++) acc[mi][ni][q] = 0.f;

    int rr[4], ss[4];
    #pragma unroll
    for (int j = 0; j < 4; j++) { int idx = tid + j * 256; rr[j] = idx >> 3; ss[j] = idx & 7; }
    uint32_t sm0 = smem_u32(smb);

    int iters = K >> 6;
    int lrow = lane & 15;
    int lcg = (lane >> 4) << 3;

    #define STAGE(ck, bsel) do {                                                          \
        int k0_ = (ck) << 6;                                                              \
        uint32_t da = sm0 + (bsel) * TB_STAGE_BYTES;                                      \
        uint32_t db = da + TB_BUF * 2;                                                    \
        _Pragma("unroll")                                                                 \
        for (int j = 0; j < 4; j++)                                                       \
            cpa16(da + (rr[j] * BSTR64 + ss[j] * 8) * 2,                                  \
                  A + (size_t)(m0 + rr[j]) * lda + k0_ + ss[j] * 8, 16u);                 \
        _Pragma("unroll")                                                                 \
        for (int j = 0; j < 4; j++) {                                                     \
            int n = n0 + rr[j];                                                           \
            uint32_t sz = (n < N) ? 16u : 0u;                                             \
            cpa16(db + (rr[j] * BSTR64 + ss[j] * 8) * 2,                                  \
                  B + (size_t)(n < N ? n : 0) * ldb + k0_ + ss[j] * 8, sz);               \
        }                                                                                 \
        CP_COMMIT();                                                                      \
    } while (0)

    STAGE(0, 0);
    STAGE(1, 1);

    int bc = 0;
    for (int it = 0; it < iters; it++) {
        CP_WAIT1();
        __syncthreads();
        int bs = bc + 2; if (bs >= 3) bs -= 3;
        if (it + 2 < iters) STAGE(it + 2, bs);
        uint32_t ab = sm0 + bc * TB_STAGE_BYTES;
        uint32_t bb = ab + TB_BUF * 2;
        #pragma unroll
        for (int ks = 0; ks < 4; ks++) {
            int kofs = ks * 16 + lcg;
            uint32_t a[4][4], b[4][2];
            #pragma unroll
            for (int mi = 0; mi < 4; mi++)
                ldsm4(a[mi], ab + ((wm * 64 + mi * 16 + lrow) * BSTR64 + kofs) * 2);
            #pragma unroll
            for (int np = 0; np < 2; np++) {
                uint32_t r[4];
                ldsm4(r, bb + ((wn * 32 + np * 16 + lrow) * BSTR64 + kofs) * 2);
                b[2 * np][0] = r[0]; b[2 * np + 1][0] = r[1];
                b[2 * np][1] = r[2]; b[2 * np + 1][1] = r[3];
            }
            #pragma unroll
            for (int mi = 0; mi < 4; mi++)
                #pragma unroll
                for (int ni = 0; ni < 4; ni++)
                    mma16(acc[mi][ni], a[mi], b[ni]);
        }
        bc++; if (bc == 3) bc = 0;
    }

    float rs[4][2] = {{0.f, 0.f}, {0.f, 0.f}, {0.f, 0.f}, {0.f, 0.f}};
    #pragma unroll
    for (int mi = 0; mi < 4; mi++) {
        int row0 = m0 + wm * 64 + mi * 16 + gid;
        #pragma unroll
        for (int ni = 0; ni < 4; ni++) {
            int col = n0 + wn * 32 + ni * 8 + tig * 2;
            #pragma unroll
            for (int half = 0; half < 2; half++) {
                int r = row0 + half * 8;
                float v0 = acc[mi][ni][half * 2 + 0];
                float v1 = acc[mi][ni][half * 2 + 1];
                if (bias) { v0 += bias[col]; v1 += (col + 1 < N) ? bias[col + 1] : 0.f; }
                if (addM) {
                    int ar = r % addRowMod;
                    v0 += addM[(size_t)ar * N + col];
                    if (col + 1 < N) v1 += addM[(size_t)ar * N + col + 1];
                }
                if (C) {
                    if (col < N)     C[(size_t)r * N + col]     = v0;
                    if (col + 1 < N) C[(size_t)r * N + col + 1] = v1;
                } else {
                    if (col + 1 < N) {
                        __nv_bfloat162 p = __floats2bfloat162_rn(v0, v1);
                        *(uint32_t*)(Cb + (size_t)r * NV + col) = *(uint32_t*)&p;
                        if (psum) {
                            float2 fb = __bfloat1622float2(p);
                            rs[mi][half] += __expf(fb.x) + __expf(fb.y);
                        }
                    } else if (col < N) {
                        __nv_bfloat16 h0 = __float2bfloat16(v0);
                        Cb[(size_t)r * NV + col] = h0;
                        if (psum) rs[mi][half] += __expf(__bfloat162float(h0));
                    }
                }
            }
        }
    }
    if (psum) {
        __syncthreads();                 // all warps done with mainloop smem
        float* sd = (float*)smb;         // reuse: 4 x 128 floats
        #pragma unroll
        for (int mi = 0; mi < 4; mi++)
            #pragma unroll
            for (int half = 0; half < 2; half++) {
                float s = rs[mi][half];
                s += __shfl_xor_sync(0xffffffffu, s, 1);
                s += __shfl_xor_sync(0xffffffffu, s, 2);
                if (tig == 0) sd[wn * 128 + wm * 64 + mi * 16 + half * 8 + gid] = s;
            }
        __syncthreads();
        if (tid < 128) {
            float s = (sd[tid] + sd[128 + tid]) + (sd[256 + tid] + sd[384 + tid]);
            psum[(size_t)(m0 + tid) * 80 + blockIdx.x] = s;
        }
    }
    #undef STAGE
}

// ---------------- lse[r] = log(sum over 79 tiles) ----------------
__global__ void k_lse() {
    int r = blockIdx.x * 256 + threadIdx.x;
    if (r >= TBR) return;
    const float* p = d_psum + (size_t)r * 80;
    float s = 0.f;
    #pragma unroll 4
    for (int i = 0; i < NTILES; i++) s += p[i];
    d_lse[r] = logf(s);
}

// ======================= persistent recurrence (bf16 mma + ldmatrix) ==========
__device__ __forceinline__ void grid_barrier(unsigned nb) {
    __syncthreads();
    if (threadIdx.x == 0) {
        unsigned gen = *((volatile unsigned*)&d_barGen);
        __threadfence();
        if (atomicAdd(&d_barCount, 1u) == nb - 1u) {
            d_barCount = 0u;
            __threadfence();
            atomicAdd(&d_barGen, 1u);
        } else {
            while (*((volatile unsigned*)&d_barGen) == gen) {}
        }
        __threadfence();
    }
    __syncthreads();
}

#define RSTR2 520
#define RS_SMEM2 ((64 + 32) * RSTR2 * 2)

__global__ void __launch_bounds__(256, 1) k_recur(const float* __restrict__ Whh) {
    extern __shared__ __nv_bfloat16 rs[];
    __nv_bfloat16* Bs = rs;
    __nv_bfloat16* As = rs + 64 * RSTR2;
    int bid = blockIdx.x, tid = threadIdx.x;
    int mt = bid >> 5, nt = bid & 31;
    int lane = tid & 31, wid = tid >> 5;
    int wm = wid & 1, wn = wid >> 1;
    int gid = lane >> 2, tig = lane & 3;
    int lrow = lane & 15;
    int lcg = (lane >> 4) << 3;

    for (int i = tid; i < 64 * 128; i += 256) {
        int r = i >> 7, q = (i & 127) << 2;
        int w = ((r & 3) << 9) + (nt << 4) + (r >> 2);
        float4 v = *(const float4*)(Whh + (size_t)w * NH + q);
        __nv_bfloat162 p0 = __floats2bfloat162_rn(v.x, v.y);
        __nv_bfloat162 p1 = __floats2bfloat162_rn(v.z, v.w);
        uint2 pk; pk.x = *(uint32_t*)&p0; pk.y = *(uint32_t*)&p1;
        *(uint2*)(Bs + r * RSTR2 + q) = pk;
    }

    int mrow0 = mt * 32 + wm * 16 + gid;
    int g0 = (2 * tig) & 3, g1 = (2 * tig + 1) & 3;
    float creg[2][2];
    int jcol[2], gp0_[2], gp1_[2];
    #pragma unroll
    for (int ni = 0; ni < 2; ni++) {
        int jj = wn * 4 + ni * 2 + (tig >> 1);
        int j = nt * 16 + jj;
        jcol[ni] = j;
        gp0_[ni] = g0 * 512 + j;
        gp1_[ni] = g1 * 512 + j;
        creg[ni][0] = d_c0[mrow0 * NH + j];
        creg[ni][1] = d_c0[(mrow0 + 8) * NH + j];
    }

    uint32_t sB0 = smem_u32(Bs), sA0 = smem_u32(As);
    uint32_t aAddr = sA0 + ((wm * 16 + lrow) * RSTR2 + lcg) * 2;
    uint32_t bAddr = sB0 + ((wn * 16 + lrow) * RSTR2 + lcg) * 2;

    for (int t = 0; t < NT; t++) {
        const __nv_bfloat16* hsrc = (t == 0) ? d_h0_bf : (d_hall_bf + (size_t)(t - 1) * NB * NH);
        for (int i = tid; i < 32 * 64; i += 256) {
            int r = i >> 6, q = (i & 63) << 3;
            *(uint4*)(As + r * RSTR2 + q) = *(const uint4*)(hsrc + (size_t)(mt * 32 + r) * NH + q);
        }
        __syncthreads();

        float acc[2][4] = {{0.f, 0.f, 0.f, 0.f}, {0.f, 0.f, 0.f, 0.f}};
        #pragma unroll 8
        for (int kc = 0; kc < 512; kc += 16) {
            uint32_t a[4], r[4];
            ldsm4(a, aAddr + kc * 2);
            ldsm4(r, bAddr + kc * 2);
            uint32_t b0[2] = { r[0], r[2] };
            uint32_t b1[2] = { r[1], r[3] };
            mma16(acc[0], a, b0);
            mma16(acc[1], a, b1);
        }

        const float* gp = d_gpre + (size_t)t * NB * G4;
        __nv_bfloat16* hb = d_hall_bf + (size_t)t * NB * NH;
        #pragma unroll
        for (int ni = 0; ni < 2; ni++) {
            float v0 = acc[ni][0] + gp[(size_t)mrow0 * G4 + gp0_[ni]];
            float v1 = acc[ni][1] + gp[(size_t)mrow0 * G4 + gp1_[ni]];
            float v2 = acc[ni][2] + gp[(size_t)(mrow0 + 8) * G4 + gp0_[ni]];
            float v3 = acc[ni][3] + gp[(size_t)(mrow0 + 8) * G4 + gp1_[ni]];
            float w0 = __shfl_xor_sync(0xffffffffu, v0, 1);
            float w1 = __shfl_xor_sync(0xffffffffu, v1, 1);
            float w2 = __shfl_xor_sync(0xffffffffu, v2, 1);
            float w3 = __shfl_xor_sync(0xffffffffu, v3, 1);
            float iA, fA, gA, oA, iB, fB, gB, oB;
            if ((tig & 1) == 0) { iA = v0; fA = v1; gA = w0; oA = w1; iB = v2; fB = v3; gB = w2; oB = w3; }
            else                { iA = w0; fA = w1; gA = v0; oA = v1; iB = w2; fB = w3; gB = v2; oB = v3; }
            float c0n = sigmoidf_(fA) * creg[ni][0] + sigmoidf_(iA) * tanhf(gA);
            float h0v = sigmoidf_(oA) * tanhf(c0n);
            creg[ni][0] = c0n;
            float c1n = sigmoidf_(fB) * creg[ni][1] + sigmoidf_(iB) * tanhf(gB);
            float h1v = sigmoidf_(oB) * tanhf(c1n);
            creg[ni][1] = c1n;
            if ((tig & 1) == 0) {
                hb[(size_t)mrow0 * NH + jcol[ni]] = __float2bfloat16(h0v);
                hb[(size_t)(mrow0 + 8) * NH + jcol[ni]] = __float2bfloat16(h1v);
            }
        }
        grid_barrier(gridDim.x);
    }
}

// ======================= single-pass output (bf16 logits + lse -> fp32 x2) ============
#define NV8 1250   // NV / 8

__global__ void __launch_bounds__(256) k_out(float* __restrict__ out) {
    int r = blockIdx.x;
    float sh = d_lse[r];
    const uint4* L = (const uint4*)(d_logits_bf + (size_t)r * NV);
    float4* o1 = (float4*)(out + (size_t)r * NV);
    float4* o2 = (float4*)(out + (size_t)TBR * NV + (size_t)r * NV);
    for (int v = threadIdx.x; v < NV8; v += 256) {
        uint4 u = L[v];
        float2 f0 = __bfloat1622float2(*(__nv_bfloat162*)&u.x);
        float2 f1 = __bfloat1622float2(*(__nv_bfloat162*)&u.y);
        float2 f2 = __bfloat1622float2(*(__nv_bfloat162*)&u.z);
        float2 f3 = __bfloat1622float2(*(__nv_bfloat162*)&u.w);
        float4 lpA = make_float4(f0.x - sh, f0.y - sh, f1.x - sh, f1.y - sh);
        float4 lpB = make_float4(f2.x - sh, f2.y - sh, f3.x - sh, f3.y - sh);
        float4 pA = make_float4(__expf(lpA.x), __expf(lpA.y), __expf(lpA.z), __expf(lpA.w));
        float4 pB = make_float4(__expf(lpB.x), __expf(lpB.y), __expf(lpB.z), __expf(lpB.w));
        o1[2 * v] = lpA; o1[2 * v + 1] = lpB;
        o2[2 * v] = pA;  o2[2 * v + 1] = pB;
    }
}

// ======================= launch =======================
extern "C" void kernel_launch(void* const* d_in, const int* in_sizes, int n_in,
                              void* d_out, int out_size) {
    const float* features = (const float*)d_in[0];
    const int*   captions = (const int*)d_in[1];
    const float* W_init_h = (const float*)d_in[2];
    const float* W_init_c = (const float*)d_in[3];
    const float* Wv       = (const float*)d_in[4];
    const float* bv       = (const float*)d_in[5];
    // d_in[6]=Wa, d_in[7]=ba unused (softmax shift-invariance)
    const float* embed    = (const float*)d_in[8];
    const float* W_ih     = (const float*)d_in[9];
    const float* W_hh     = (const float*)d_in[10];
    const float* b_ih     = (const float*)d_in[11];
    const float* b_hh     = (const float*)d_in[12];
    const float* Wo       = (const float*)d_in[13];
    const float* bo       = (const float*)d_in[14];
    float* out = (float*)d_out;

    float *p_gctx, *p_gpre, *p_psum;
    __nv_bfloat16 *p_ebf, *p_wobf, *p_wibf, *p_hbf, *p_lbf;
    cudaGetSymbolAddress((void**)&p_gctx,   d_gctx);
    cudaGetSymbolAddress((void**)&p_gpre,   d_gpre);
    cudaGetSymbolAddress((void**)&p_psum,   d_psum);
    cudaGetSymbolAddress((void**)&p_ebf,    d_emb_bf);
    cudaGetSymbolAddress((void**)&p_wobf,   d_wo_bf);
    cudaGetSymbolAddress((void**)&p_wibf,   d_wih_bf);
    cudaGetSymbolAddress((void**)&p_hbf,    d_hall_bf);
    cudaGetSymbolAddress((void**)&p_lbf,    d_logits_bf);

    static cudaStream_t sV = nullptr;
    static cudaEvent_t evF = nullptr, evJ = nullptr;
    if (!sV) {
        cudaFuncSetAttribute(k_recur, cudaFuncAttributeMaxDynamicSharedMemorySize, RS_SMEM2);
        cudaFuncSetAttribute(tbmma, cudaFuncAttributeMaxDynamicSharedMemorySize, TB_SMEM);
        cudaStreamCreateWithFlags(&sV, cudaStreamNonBlocking);
        cudaEventCreateWithFlags(&evF, cudaEventDisableTiming);
        cudaEventCreateWithFlags(&evJ, cudaEventDisableTiming);
    }

    // fork: visual track on sV
    cudaEventRecord(evF, 0);
    cudaStreamWaitEvent(sV, evF, 0);
    k_att<<<dim3(25, NB), 256, 0, sV>>>(features, Wv, bv);
    k_ctx<<<dim3(4, NB), 256, 0, sV>>>(features);
    k_init<<<dim3(48, 4), 256, 0, sV>>>(W_init_h, W_init_c, W_ih, b_ih, b_hh);
    cudaEventRecord(evJ, sV);

    // track B on main stream: gather + conversions
    k_gather<<<TBR, NE>>>(captions, embed);
    k_cvtb<<<(G4 * NE / 4 + 255) / 256, 256>>>(W_ih + VDIM, VDIM + NE, NE, p_wibf, G4 * NE / 4);
    k_cvtb<<<(NV * NH / 4 + 255) / 256, 256>>>(Wo, NH, NH, p_wobf, NV * NH / 4);

    // join
    cudaStreamWaitEvent(0, evJ, 0);

    // g_pre = emb @ WihE^T + g_ctx[b]  (bf16 mma, fp32 out)
    tbmma<<<dim3(G4 / 128, TBR / 128), 256, TB_SMEM>>>(
        p_ebf, NE, p_wibf, NE, p_gpre, nullptr, TBR, G4, NE, nullptr, p_gctx, NB, nullptr);

    // recurrence (bf16 mma + ldmatrix, 1 grid barrier / step)
    k_recur<<<NB, 256, RS_SMEM2>>>(W_hh);

    // logits = hall @ Wo^T + bo  (bf16 mma, bf16 out + fused partial expsum)
    tbmma<<<dim3(NTILES, TBR / 128), 256, TB_SMEM>>>(
        p_hbf, NH, p_wobf, NH, nullptr, p_lbf, TBR, NV, NH, bo, nullptr, 0, p_psum);

    // lse + single-pass outputs
    k_lse<<<(TBR + 255) / 256, 256>>>();
    k_out<<<TBR, 256>>>(out);
}

// round 15
// speedup vs baseline: 1.0627x; 1.0627x over previous
#include <cuda_runtime.h>
#include <cuda_bf16.h>
#include <math.h>
#include <stdint.h>

// Problem dims
#define NB   128
#define NT   20
#define VNUM 196
#define VDIM 512
#define NE   256
#define NH   512
#define NV   10000
#define G4   2048
#define TBR  2560   // NT*NB

// ---------------- helpers ----------------
__device__ __forceinline__ void mma16(float* c, const uint32_t* a, const uint32_t* b) {
    asm volatile("mma.sync.aligned.m16n8k16.row.col.f32.bf16.bf16.f32 "
                 "{%0,%1,%2,%3}, {%4,%5,%6,%7}, {%8,%9}, {%0,%1,%2,%3};"
                 : "+f"(c[0]), "+f"(c[1]), "+f"(c[2]), "+f"(c[3])
                 : "r"(a[0]), "r"(a[1]), "r"(a[2]), "r"(a[3]), "r"(b[0]), "r"(b[1]));
}
__device__ __forceinline__ uint32_t smem_u32(const void* p) {
    uint32_t a;
    asm("{ .reg .u64 t; cvta.to.shared.u64 t, %1; cvt.u32.u64 %0, t; }" : "=r"(a) : "l"(p));
    return a;
}
__device__ __forceinline__ void ldsm4(uint32_t* r, uint32_t addr) {
    asm volatile("ldmatrix.sync.aligned.m8n8.x4.shared.b16 {%0,%1,%2,%3}, [%4];"
                 : "=r"(r[0]), "=r"(r[1]), "=r"(r[2]), "=r"(r[3]) : "r"(addr));
}
__device__ __forceinline__ void cpa16(uint32_t saddr, const void* gaddr, uint32_t srcsz) {
    asm volatile("cp.async.cg.shared.global [%0], [%1], 16, %2;"
                 :: "r"(saddr), "l"(gaddr), "r"(srcsz));
}
#define CP_COMMIT() asm volatile("cp.async.commit_group;")
#define CP_WAIT1()  asm volatile("cp.async.wait_group 1;")
__device__ __forceinline__ float sigmoidf_(float x) { return 1.f / (1.f + __expf(-x)); }

// ---------------- scratch ----------------
__device__ __nv_bfloat16 d_emb_bf[TBR * NE];
__device__ __nv_bfloat16 d_wo_bf[(size_t)NV * NH];
__device__ __nv_bfloat16 d_wih_bf[G4 * NE];
__device__ __nv_bfloat16 d_hall_bf[(size_t)TBR * NH];
__device__ __nv_bfloat16 d_h0_bf[NB * NH];
__device__ __nv_bfloat16 d_logits_bf[(size_t)TBR * (NV + 16)];
__device__ float d_attv[NB * VNUM];
__device__ float d_feat_sum[NB * VDIM];
__device__ float d_ctx[NB * VDIM];
__device__ float d_c0[NB * NH];
__device__ float d_gctx[NB * G4];
__device__ float d_gpre[(size_t)TBR * G4];
__device__ unsigned d_barCount;
__device__ unsigned d_barGen;

// ---------------- embedding gather -> bf16 ----------------
__global__ void k_gather(const int* __restrict__ cap, const float* __restrict__ et) {
    int r = blockIdx.x;                 // t*NB + b
    int t = r / NB, b = r % NB;
    int id = cap[b * NT + t];
    d_emb_bf[(size_t)r * NE + threadIdx.x] = __float2bfloat16(et[(size_t)id * NE + threadIdx.x]);
}

// ---------------- fp32 -> bf16 (4 elems/thread, packed 8B stores) ----------------
__global__ void k_cvtb(const float* __restrict__ src, int pitch, int cols,
                       __nv_bfloat16* __restrict__ dst, int n4) {
    int i = blockIdx.x * 256 + threadIdx.x;
    if (i >= n4) return;
    int e = i * 4;
    const float* s;
    if (pitch == cols) {
        s = src + e;
    } else {
        int r = e / cols, c = e % cols;
        s = src + (size_t)r * pitch + c;
    }
    float4 v = *(const float4*)s;
    __nv_bfloat162 p0 = __floats2bfloat162_rn(v.x, v.y);
    __nv_bfloat162 p1 = __floats2bfloat162_rn(v.z, v.w);
    uint2 pk;
    pk.x = *(uint32_t*)&p0;
    pk.y = *(uint32_t*)&p1;
    *(uint2*)(dst + e) = pk;
}

// ---------------- attention logits: one warp per (b, n) ----------------
__global__ void __launch_bounds__(256) k_att(const float* __restrict__ feat,
        const float* __restrict__ Wv, const float* __restrict__ bv) {
    int warp = threadIdx.x >> 5, lane = threadIdx.x & 31;
    int b = blockIdx.y;
    int n = blockIdx.x * 8 + warp;
    if (n >= VNUM) return;
    const float* fr = feat + ((size_t)b * VNUM + n) * VDIM;
    float acc = 0.f;
    #pragma unroll
    for (int k = lane; k < VDIM; k += 32) acc += fr[k] * Wv[k];
    #pragma unroll
    for (int o = 16; o; o >>= 1) acc += __shfl_xor_sync(0xffffffffu, acc, o);
    if (lane == 0) d_attv[b * VNUM + n] = acc + bv[0];
}

// ---------------- softmax(attv) -> feat_sum + ctx ----------------
__global__ void __launch_bounds__(256) k_ctx(const float* __restrict__ feat) {
    __shared__ float salpha[VNUM];
    __shared__ float red[256];
    __shared__ float sfs[256];
    __shared__ float sctx[256];
    int b = blockIdx.y, tid = threadIdx.x;
    int v0 = blockIdx.x * 128;
    float x = (tid < VNUM) ? d_attv[b * VNUM + tid] : -1e30f;
    red[tid] = x; __syncthreads();
    for (int s = 128; s; s >>= 1) { if (tid < s) red[tid] = fmaxf(red[tid], red[tid + s]); __syncthreads(); }
    float mx = red[0]; __syncthreads();
    float e = (tid < VNUM) ? __expf(x - mx) : 0.f;
    red[tid] = e; __syncthreads();
    for (int s = 128; s; s >>= 1) { if (tid < s) red[tid] += red[tid + s]; __syncthreads(); }
    float inv = 1.f / red[0];
    __syncthreads();
    if (tid < VNUM) salpha[tid] = e * inv;
    __syncthreads();

    int v = v0 + (tid & 127);
    int half = tid >> 7;
    int n0 = half * 98, n1 = n0 + 98;
    if (n1 > VNUM) n1 = VNUM;
    const float* fp = feat + (size_t)b * VNUM * VDIM + v;
    float fs = 0.f, c0 = 0.f, c1 = 0.f, c2 = 0.f, c3 = 0.f;
    int n = n0;
    for (; n + 4 <= n1; n += 4) {
        float x0 = fp[(size_t)n * VDIM];
        float x1 = fp[(size_t)(n + 1) * VDIM];
        float x2 = fp[(size_t)(n + 2) * VDIM];
        float x3 = fp[(size_t)(n + 3) * VDIM];
        fs += (x0 + x1) + (x2 + x3);
        c0 += salpha[n] * x0; c1 += salpha[n + 1] * x1;
        c2 += salpha[n + 2] * x2; c3 += salpha[n + 3] * x3;
    }
    for (; n < n1; n++) { float xx = fp[(size_t)n * VDIM]; fs += xx; c0 += salpha[n] * xx; }
    sfs[tid] = fs;
    sctx[tid] = (c0 + c1) + (c2 + c3);
    __syncthreads();
    if (half == 0) {
        d_feat_sum[b * VDIM + v] = sfs[tid] + sfs[tid + 128];
        d_ctx[b * VDIM + v] = sctx[tid] + sctx[tid + 128];
    }
}

// ---------------- fused init GEMMs: h0(bf16) | c0 | g_ctx (N=3072 concat) ----------------
__global__ void __launch_bounds__(256) k_init(
        const float* __restrict__ Wini_h, const float* __restrict__ Wini_c,
        const float* __restrict__ Wih,
        const float* __restrict__ bih, const float* __restrict__ bhh) {
    __shared__ float As[16][32];
    __shared__ float Bs[16][64];
    int ntile = blockIdx.x, mt = blockIdx.y;
    int seg, nloc0;
    const float* A;
    const float* B;
    int ldb;
    if (ntile < 8)       { seg = 0; nloc0 = ntile * 64;        A = d_feat_sum; B = Wini_h; ldb = VDIM; }
    else if (ntile < 16) { seg = 1; nloc0 = (ntile - 8) * 64;  A = d_feat_sum; B = Wini_c; ldb = VDIM; }
    else                 { seg = 2; nloc0 = (ntile - 16) * 64; A = d_ctx;      B = Wih;    ldb = VDIM + NE; }
    int tid = threadIdx.x;
    int tx = tid & 15, ty = tid >> 4;
    int m0 = mt * 32;
    float acc[2][4] = {{0.f, 0.f, 0.f, 0.f}, {0.f, 0.f, 0.f, 0.f}};
    for (int k0 = 0; k0 < VDIM; k0 += 16) {
        {
            int i = tid; int r = i >> 4, kk = i & 15;
            As[kk][r] = A[(size_t)(m0 + r) * VDIM + k0 + kk];
            i = tid + 256; r = i >> 4; kk = i & 15;
            As[kk][r] = A[(size_t)(m0 + r) * VDIM + k0 + kk];
        }
        #pragma unroll
        for (int j = 0; j < 4; j++) {
            int i = tid + j * 256; int r = i >> 4, kk = i & 15;
            Bs[kk][r] = B[(size_t)(nloc0 + r) * ldb + k0 + kk];
        }
        __syncthreads();
        #pragma unroll
        for (int kk = 0; kk < 16; kk++) {
            float a0 = As[kk][ty * 2], a1 = As[kk][ty * 2 + 1];
            float b0 = Bs[kk][tx * 4], b1 = Bs[kk][tx * 4 + 1];
            float b2 = Bs[kk][tx * 4 + 2], b3 = Bs[kk][tx * 4 + 3];
            acc[0][0] += a0 * b0; acc[0][1] += a0 * b1; acc[0][2] += a0 * b2; acc[0][3] += a0 * b3;
            acc[1][0] += a1 * b0; acc[1][1] += a1 * b1; acc[1][2] += a1 * b2; acc[1][3] += a1 * b3;
        }
        __syncthreads();
    }
    #pragma unroll
    for (int i = 0; i < 2; i++) {
        int m = m0 + ty * 2 + i;
        #pragma unroll
        for (int j = 0; j < 4; j++) {
            int n = nloc0 + tx * 4 + j;
            if (seg == 0) {
                d_h0_bf[(size_t)m * NH + n] = __float2bfloat16(acc[i][j] * (1.f / VNUM));
            } else if (seg == 1) {
                d_c0[(size_t)m * NH + n] = acc[i][j] * (1.f / VNUM);
            } else {
                d_gctx[(size_t)m * G4 + n] = acc[i][j] + bih[n] + bhh[n];
            }
        }
    }
}

// ======================= bf16 mma GEMM: BK=64, 3-stage cp.async, 2 CTAs/SM =========
#define BSTR64 72
#define TB_BUF (128 * BSTR64)
#define TB_STAGE_BYTES (2 * TB_BUF * 2)
#define TB_SMEM (3 * TB_STAGE_BYTES)

__global__ void __launch_bounds__(256, 2) tbmma(const __nv_bfloat16* __restrict__ A, int lda,
        const __nv_bfloat16* __restrict__ B, int ldb,
        float* __restrict__ C, __nv_bfloat16* __restrict__ Cb,
        int M, int N, int K,
        const float* __restrict__ bias, const float* __restrict__ addM, int addRowMod) {
    extern __shared__ __align__(16) __nv_bfloat16 smb[];
    int tid = threadIdx.x, lane = tid & 31, wid = tid >> 5;
    int wm = wid & 1, wn = wid >> 1;
    int m0 = blockIdx.y * 128, n0 = blockIdx.x * 128;
    int gid = lane >> 2, tig = lane & 3;

    float acc[4][4][4];
    #pragma unroll
    for (int mi = 0; mi < 4; mi++)
        #pragma unroll
        for (int ni = 0; ni < 4; ni++)
            #pragma unroll
            for (int q = 0; q < 4; q++) acc[mi][ni][q] = 0.f;

    int rr[4], ss[4];
    #pragma unroll
    for (int j = 0; j < 4; j++) { int idx = tid + j * 256; rr[j] = idx >> 3; ss[j] = idx & 7; }
    uint32_t sm0 = smem_u32(smb);

    int iters = K >> 6;
    int lrow = lane & 15;
    int lcg = (lane >> 4) << 3;

    #define STAGE(ck, bsel) do {                                                          \
        int k0_ = (ck) << 6;                                                              \
        uint32_t da = sm0 + (bsel) * TB_STAGE_BYTES;                                      \
        uint32_t db = da + TB_BUF * 2;                                                    \
        _Pragma("unroll")                                                                 \
        for (int j = 0; j < 4; j++)                                                       \
            cpa16(da + (rr[j] * BSTR64 + ss[j] * 8) * 2,                                  \
                  A + (size_t)(m0 + rr[j]) * lda + k0_ + ss[j] * 8, 16u);                 \
        _Pragma("unroll")                                                                 \
        for (int j = 0; j < 4; j++) {                                                     \
            int n = n0 + rr[j];                                                           \
            uint32_t sz = (n < N) ? 16u : 0u;                                             \
            cpa16(db + (rr[j] * BSTR64 + ss[j] * 8) * 2,                                  \
                  B + (size_t)(n < N ? n : 0) * ldb + k0_ + ss[j] * 8, sz);               \
        }                                                                                 \
        CP_COMMIT();                                                                      \
    } while (0)

    STAGE(0, 0);
    STAGE(1, 1);

    int bc = 0;
    for (int it = 0; it < iters; it++) {
        CP_WAIT1();
        __syncthreads();
        int bs = bc + 2; if (bs >= 3) bs -= 3;
        if (it + 2 < iters) STAGE(it + 2, bs);
        uint32_t ab = sm0 + bc * TB_STAGE_BYTES;
        uint32_t bb = ab + TB_BUF * 2;
        #pragma unroll
        for (int ks = 0; ks < 4; ks++) {
            int kofs = ks * 16 + lcg;
            uint32_t a[4][4], b[4][2];
            #pragma unroll
            for (int mi = 0; mi < 4; mi++)
                ldsm4(a[mi], ab + ((wm * 64 + mi * 16 + lrow) * BSTR64 + kofs) * 2);
            #pragma unroll
            for (int np = 0; np < 2; np++) {
                uint32_t r[4];
                ldsm4(r, bb + ((wn * 32 + np * 16 + lrow) * BSTR64 + kofs) * 2);
                b[2 * np][0] = r[0]; b[2 * np + 1][0] = r[1];
                b[2 * np][1] = r[2]; b[2 * np + 1][1] = r[3];
            }
            #pragma unroll
            for (int mi = 0; mi < 4; mi++)
                #pragma unroll
                for (int ni = 0; ni < 4; ni++)
                    mma16(acc[mi][ni], a[mi], b[ni]);
        }
        bc++; if (bc == 3) bc = 0;
    }

    #pragma unroll
    for (int mi = 0; mi < 4; mi++) {
        int row0 = m0 + wm * 64 + mi * 16 + gid;
        #pragma unroll
        for (int ni = 0; ni < 4; ni++) {
            int col = n0 + wn * 32 + ni * 8 + tig * 2;
            #pragma unroll
            for (int half = 0; half < 2; half++) {
                int r = row0 + half * 8;
                float v0 = acc[mi][ni][half * 2 + 0];
                float v1 = acc[mi][ni][half * 2 + 1];
                if (bias) { v0 += bias[col]; v1 += (col + 1 < N) ? bias[col + 1] : 0.f; }
                if (addM) {
                    int ar = r % addRowMod;
                    v0 += addM[(size_t)ar * N + col];
                    if (col + 1 < N) v1 += addM[(size_t)ar * N + col + 1];
                }
                if (C) {
                    if (col < N)     C[(size_t)r * N + col]     = v0;
                    if (col + 1 < N) C[(size_t)r * N + col + 1] = v1;
                } else {
                    if (col + 1 < N) {
                        __nv_bfloat162 p = __floats2bfloat162_rn(v0, v1);
                        *(uint32_t*)(Cb + (size_t)r * NV + col) = *(uint32_t*)&p;
                    } else if (col < N) {
                        Cb[(size_t)r * NV + col] = __float2bfloat16(v0);
                    }
                }
            }
        }
    }
    #undef STAGE
}

// ======================= persistent recurrence (bf16 mma + ldmatrix) ==========
__device__ __forceinline__ void grid_barrier(unsigned nb) {
    __syncthreads();
    if (threadIdx.x == 0) {
        unsigned gen = *((volatile unsigned*)&d_barGen);
        __threadfence();
        if (atomicAdd(&d_barCount, 1u) == nb - 1u) {
            d_barCount = 0u;
            __threadfence();
            atomicAdd(&d_barGen, 1u);
        } else {
            while (*((volatile unsigned*)&d_barGen) == gen) {}
        }
        __threadfence();
    }
    __syncthreads();
}

#define RSTR2 520
#define RS_SMEM2 ((64 + 32) * RSTR2 * 2)

__global__ void __launch_bounds__(256, 1) k_recur(const float* __restrict__ Whh) {
    extern __shared__ __nv_bfloat16 rs[];
    __nv_bfloat16* Bs = rs;
    __nv_bfloat16* As = rs + 64 * RSTR2;
    int bid = blockIdx.x, tid = threadIdx.x;
    int mt = bid >> 5, nt = bid & 31;
    int lane = tid & 31, wid = tid >> 5;
    int wm = wid & 1, wn = wid >> 1;
    int gid = lane >> 2, tig = lane & 3;
    int lrow = lane & 15;
    int lcg = (lane >> 4) << 3;

    for (int i = tid; i < 64 * 128; i += 256) {
        int r = i >> 7, q = (i & 127) << 2;
        int w = ((r & 3) << 9) + (nt << 4) + (r >> 2);
        float4 v = *(const float4*)(Whh + (size_t)w * NH + q);
        __nv_bfloat162 p0 = __floats2bfloat162_rn(v.x, v.y);
        __nv_bfloat162 p1 = __floats2bfloat162_rn(v.z, v.w);
        uint2 pk; pk.x = *(uint32_t*)&p0; pk.y = *(uint32_t*)&p1;
        *(uint2*)(Bs + r * RSTR2 + q) = pk;
    }

    int mrow0 = mt * 32 + wm * 16 + gid;
    int g0 = (2 * tig) & 3, g1 = (2 * tig + 1) & 3;
    float creg[2][2];
    int jcol[2], gp0_[2], gp1_[2];
    #pragma unroll
    for (int ni = 0; ni < 2; ni++) {
        int jj = wn * 4 + ni * 2 + (tig >> 1);
        int j = nt * 16 + jj;
        jcol[ni] = j;
        gp0_[ni] = g0 * 512 + j;
        gp1_[ni] = g1 * 512 + j;
        creg[ni][0] = d_c0[mrow0 * NH + j];
        creg[ni][1] = d_c0[(mrow0 + 8) * NH + j];
    }

    uint32_t sB0 = smem_u32(Bs), sA0 = smem_u32(As);
    uint32_t aAddr = sA0 + ((wm * 16 + lrow) * RSTR2 + lcg) * 2;
    uint32_t bAddr = sB0 + ((wn * 16 + lrow) * RSTR2 + lcg) * 2;

    for (int t = 0; t < NT; t++) {
        const __nv_bfloat16* hsrc = (t == 0) ? d_h0_bf : (d_hall_bf + (size_t)(t - 1) * NB * NH);
        for (int i = tid; i < 32 * 64; i += 256) {
            int r = i >> 6, q = (i & 63) << 3;
            *(uint4*)(As + r * RSTR2 + q) = *(const uint4*)(hsrc + (size_t)(mt * 32 + r) * NH + q);
        }
        __syncthreads();

        float acc[2][4] = {{0.f, 0.f, 0.f, 0.f}, {0.f, 0.f, 0.f, 0.f}};
        #pragma unroll 8
        for (int kc = 0; kc < 512; kc += 16) {
            uint32_t a[4], r[4];
            ldsm4(a, aAddr + kc * 2);
            ldsm4(r, bAddr + kc * 2);
            uint32_t b0[2] = { r[0], r[2] };
            uint32_t b1[2] = { r[1], r[3] };
            mma16(acc[0], a, b0);
            mma16(acc[1], a, b1);
        }

        const float* gp = d_gpre + (size_t)t * NB * G4;
        __nv_bfloat16* hb = d_hall_bf + (size_t)t * NB * NH;
        #pragma unroll
        for (int ni = 0; ni < 2; ni++) {
            float v0 = acc[ni][0] + gp[(size_t)mrow0 * G4 + gp0_[ni]];
            float v1 = acc[ni][1] + gp[(size_t)mrow0 * G4 + gp1_[ni]];
            float v2 = acc[ni][2] + gp[(size_t)(mrow0 + 8) * G4 + gp0_[ni]];
            float v3 = acc[ni][3] + gp[(size_t)(mrow0 + 8) * G4 + gp1_[ni]];
            float w0 = __shfl_xor_sync(0xffffffffu, v0, 1);
            float w1 = __shfl_xor_sync(0xffffffffu, v1, 1);
            float w2 = __shfl_xor_sync(0xffffffffu, v2, 1);
            float w3 = __shfl_xor_sync(0xffffffffu, v3, 1);
            float iA, fA, gA, oA, iB, fB, gB, oB;
            if ((tig & 1) == 0) { iA = v0; fA = v1; gA = w0; oA = w1; iB = v2; fB = v3; gB = w2; oB = w3; }
            else                { iA = w0; fA = w1; gA = v0; oA = v1; iB = w2; fB = w3; gB = v2; oB = v3; }
            float c0n = sigmoidf_(fA) * creg[ni][0] + sigmoidf_(iA) * tanhf(gA);
            float h0v = sigmoidf_(oA) * tanhf(c0n);
            creg[ni][0] = c0n;
            float c1n = sigmoidf_(fB) * creg[ni][1] + sigmoidf_(iB) * tanhf(gB);
            float h1v = sigmoidf_(oB) * tanhf(c1n);
            creg[ni][1] = c1n;
            if ((tig & 1) == 0) {
                hb[(size_t)mrow0 * NH + jcol[ni]] = __float2bfloat16(h0v);
                hb[(size_t)(mrow0 + 8) * NH + jcol[ni]] = __float2bfloat16(h1v);
            }
        }
        grid_barrier(gridDim.x);
    }
}

// ======================= output softmax (bf16 logits, register-cached row) ============
#define NV8 1250   // NV / 8

__global__ void __launch_bounds__(512) k_out(float* __restrict__ out) {
    __shared__ float red[512];
    int r = blockIdx.x, tid = threadIdx.x;
    const uint4* L = (const uint4*)(d_logits_bf + (size_t)r * NV);
    uint4 cache[3];
    float mx = -1e30f;
    #pragma unroll
    for (int j = 0; j < 3; j++) {
        int v = tid + j * 512;
        if (v < NV8) {
            uint4 u = L[v];
            cache[j] = u;
            float2 f0 = __bfloat1622float2(*(__nv_bfloat162*)&u.x);
            float2 f1 = __bfloat1622float2(*(__nv_bfloat162*)&u.y);
            float2 f2 = __bfloat1622float2(*(__nv_bfloat162*)&u.z);
            float2 f3 = __bfloat1622float2(*(__nv_bfloat162*)&u.w);
            mx = fmaxf(mx, fmaxf(fmaxf(f0.x, f0.y), fmaxf(f1.x, f1.y)));
            mx = fmaxf(mx, fmaxf(fmaxf(f2.x, f2.y), fmaxf(f3.x, f3.y)));
        }
    }
    red[tid] = mx; __syncthreads();
    for (int s = 256; s; s >>= 1) { if (tid < s) red[tid] = fmaxf(red[tid], red[tid + s]); __syncthreads(); }
    mx = red[0]; __syncthreads();
    float sum = 0.f;
    #pragma unroll
    for (int j = 0; j < 3; j++) {
        int v = tid + j * 512;
        if (v < NV8) {
            uint4 u = cache[j];
            float2 f0 = __bfloat1622float2(*(__nv_bfloat162*)&u.x);
            float2 f1 = __bfloat1622float2(*(__nv_bfloat162*)&u.y);
            float2 f2 = __bfloat1622float2(*(__nv_bfloat162*)&u.z);
            float2 f3 = __bfloat1622float2(*(__nv_bfloat162*)&u.w);
            sum += (__expf(f0.x - mx) + __expf(f0.y - mx)) + (__expf(f1.x - mx) + __expf(f1.y - mx));
            sum += (__expf(f2.x - mx) + __expf(f2.y - mx)) + (__expf(f3.x - mx) + __expf(f3.y - mx));
        }
    }
    red[tid] = sum; __syncthreads();
    for (int s = 256; s; s >>= 1) { if (tid < s) red[tid] += red[tid + s]; __syncthreads(); }
    float sh = mx + logf(red[0]);
    float4* o1 = (float4*)(out + (size_t)r * NV);
    float4* o2 = (float4*)(out + (size_t)TBR * NV + (size_t)r * NV);
    #pragma unroll
    for (int j = 0; j < 3; j++) {
        int v = tid + j * 512;
        if (v < NV8) {
            uint4 u = cache[j];
            float2 f0 = __bfloat1622float2(*(__nv_bfloat162*)&u.x);
            float2 f1 = __bfloat1622float2(*(__nv_bfloat162*)&u.y);
            float2 f2 = __bfloat1622float2(*(__nv_bfloat162*)&u.z);
            float2 f3 = __bfloat1622float2(*(__nv_bfloat162*)&u.w);
            float4 lpA = make_float4(f0.x - sh, f0.y - sh, f1.x - sh, f1.y - sh);
            float4 lpB = make_float4(f2.x - sh, f2.y - sh, f3.x - sh, f3.y - sh);
            float4 pA = make_float4(__expf(lpA.x), __expf(lpA.y), __expf(lpA.z), __expf(lpA.w));
            float4 pB = make_float4(__expf(lpB.x), __expf(lpB.y), __expf(lpB.z), __expf(lpB.w));
            o1[2 * v] = lpA; o1[2 * v + 1] = lpB;
            o2[2 * v] = pA;  o2[2 * v + 1] = pB;
        }
    }
}

// ======================= launch =======================
extern "C" void kernel_launch(void* const* d_in, const int* in_sizes, int n_in,
                              void* d_out, int out_size) {
    const float* features = (const float*)d_in[0];
    const int*   captions = (const int*)d_in[1];
    const float* W_init_h = (const float*)d_in[2];
    const float* W_init_c = (const float*)d_in[3];
    const float* Wv       = (const float*)d_in[4];
    const float* bv       = (const float*)d_in[5];
    // d_in[6]=Wa, d_in[7]=ba unused (softmax shift-invariance)
    const float* embed    = (const float*)d_in[8];
    const float* W_ih     = (const float*)d_in[9];
    const float* W_hh     = (const float*)d_in[10];
    const float* b_ih     = (const float*)d_in[11];
    const float* b_hh     = (const float*)d_in[12];
    const float* Wo       = (const float*)d_in[13];
    const float* bo       = (const float*)d_in[14];
    float* out = (float*)d_out;

    float *p_gctx, *p_gpre;
    __nv_bfloat16 *p_ebf, *p_wobf, *p_wibf, *p_hbf, *p_lbf;
    cudaGetSymbolAddress((void**)&p_gctx,   d_gctx);
    cudaGetSymbolAddress((void**)&p_gpre,   d_gpre);
    cudaGetSymbolAddress((void**)&p_ebf,    d_emb_bf);
    cudaGetSymbolAddress((void**)&p_wobf,   d_wo_bf);
    cudaGetSymbolAddress((void**)&p_wibf,   d_wih_bf);
    cudaGetSymbolAddress((void**)&p_hbf,    d_hall_bf);
    cudaGetSymbolAddress((void**)&p_lbf,    d_logits_bf);

    static int smset = 0;
    if (!smset) {
        cudaFuncSetAttribute(k_recur, cudaFuncAttributeMaxDynamicSharedMemorySize, RS_SMEM2);
        cudaFuncSetAttribute(tbmma, cudaFuncAttributeMaxDynamicSharedMemorySize, TB_SMEM);
        smset = 1;
    }

    // setup + conversions
    k_gather<<<TBR, NE>>>(captions, embed);
    k_cvtb<<<(NV * NH / 4 + 255) / 256, 256>>>(Wo, NH, NH, p_wobf, NV * NH / 4);
    k_cvtb<<<(G4 * NE / 4 + 255) / 256, 256>>>(W_ih + VDIM, VDIM + NE, NE, p_wibf, G4 * NE / 4);

    // visual stage
    k_att<<<dim3(25, NB), 256>>>(features, Wv, bv);
    k_ctx<<<dim3(4, NB), 256>>>(features);

    // fused h0 | c0 | g_ctx
    k_init<<<dim3(48, 4), 256>>>(W_init_h, W_init_c, W_ih, b_ih, b_hh);

    // g_pre = emb @ WihE^T + g_ctx[b]  (bf16 mma, fp32 out)
    tbmma<<<dim3(G4 / 128, TBR / 128), 256, TB_SMEM>>>(
        p_ebf, NE, p_wibf, NE, p_gpre, nullptr, TBR, G4, NE, nullptr, p_gctx, NB);

    // recurrence (bf16 mma + ldmatrix, 1 grid barrier / step)
    k_recur<<<NB, 256, RS_SMEM2>>>(W_hh);

    // logits = hall @ Wo^T + bo  (bf16 mma, bf16 out)
    tbmma<<<dim3((NV + 127) / 128, TBR / 128), 256, TB_SMEM>>>(
        p_hbf, NH, p_wobf, NH, nullptr, p_lbf, TBR, NV, NH, bo, nullptr, 0);

    k_out<<<TBR, 512>>>(out);
}

// round 16
// speedup vs baseline: 1.1237x; 1.0574x over previous
#include <cuda_runtime.h>
#include <cuda_bf16.h>
#include <math.h>
#include <stdint.h>

// Problem dims
#define NB   128
#define NT   20
#define VNUM 196
#define VDIM 512
#define NE   256
#define NH   512
#define NV   10000
#define G4   2048
#define TBR  2560   // NT*NB

// ---------------- helpers ----------------
__device__ __forceinline__ void mma16(float* c, const uint32_t* a, const uint32_t* b) {
    asm volatile("mma.sync.aligned.m16n8k16.row.col.f32.bf16.bf16.f32 "
                 "{%0,%1,%2,%3}, {%4,%5,%6,%7}, {%8,%9}, {%0,%1,%2,%3};"
                 : "+f"(c[0]), "+f"(c[1]), "+f"(c[2]), "+f"(c[3])
                 : "r"(a[0]), "r"(a[1]), "r"(a[2]), "r"(a[3]), "r"(b[0]), "r"(b[1]));
}
__device__ __forceinline__ uint32_t smem_u32(const void* p) {
    uint32_t a;
    asm("{ .reg .u64 t; cvta.to.shared.u64 t, %1; cvt.u32.u64 %0, t; }" : "=r"(a) : "l"(p));
    return a;
}
__device__ __forceinline__ void ldsm4(uint32_t* r, uint32_t addr) {
    asm volatile("ldmatrix.sync.aligned.m8n8.x4.shared.b16 {%0,%1,%2,%3}, [%4];"
                 : "=r"(r[0]), "=r"(r[1]), "=r"(r[2]), "=r"(r[3]) : "r"(addr));
}
__device__ __forceinline__ void cpa16(uint32_t saddr, const void* gaddr, uint32_t srcsz) {
    asm volatile("cp.async.cg.shared.global [%0], [%1], 16, %2;"
                 :: "r"(saddr), "l"(gaddr), "r"(srcsz));
}
#define CP_COMMIT() asm volatile("cp.async.commit_group;")
#define CP_WAIT1()  asm volatile("cp.async.wait_group 1;")
__device__ __forceinline__ float sigmoidf_(float x) { return 1.f / (1.f + __expf(-x)); }

// ---------------- scratch ----------------
__device__ __nv_bfloat16 d_emb_bf[TBR * NE];
__device__ __nv_bfloat16 d_wo_bf[(size_t)NV * NH];
__device__ __nv_bfloat16 d_wih_bf[G4 * NE];
__device__ __nv_bfloat16 d_hall_bf[(size_t)TBR * NH];
__device__ __nv_bfloat16 d_h0_bf[NB * NH];
__device__ __nv_bfloat16 d_logits_bf[(size_t)TBR * (NV + 16)];
__device__ float d_attv[NB * VNUM];
__device__ float d_feat_sum[NB * VDIM];
__device__ float d_ctx[NB * VDIM];
__device__ float d_c0[NB * NH];
__device__ float d_gctx[NB * G4];
__device__ float d_gpre[(size_t)TBR * G4];
__device__ unsigned d_barCount4[4];
__device__ unsigned d_barGen4[4];

// ---------------- embedding gather -> bf16 ----------------
__global__ void k_gather(const int* __restrict__ cap, const float* __restrict__ et) {
    int r = blockIdx.x;                 // t*NB + b
    int t = r / NB, b = r % NB;
    int id = cap[b * NT + t];
    d_emb_bf[(size_t)r * NE + threadIdx.x] = __float2bfloat16(et[(size_t)id * NE + threadIdx.x]);
}

// ---------------- fp32 -> bf16 (4 elems/thread, packed 8B stores) ----------------
__global__ void k_cvtb(const float* __restrict__ src, int pitch, int cols,
                       __nv_bfloat16* __restrict__ dst, int n4) {
    int i = blockIdx.x * 256 + threadIdx.x;
    if (i >= n4) return;
    int e = i * 4;
    const float* s;
    if (pitch == cols) {
        s = src + e;
    } else {
        int r = e / cols, c = e % cols;
        s = src + (size_t)r * pitch + c;
    }
    float4 v = *(const float4*)s;
    __nv_bfloat162 p0 = __floats2bfloat162_rn(v.x, v.y);
    __nv_bfloat162 p1 = __floats2bfloat162_rn(v.z, v.w);
    uint2 pk;
    pk.x = *(uint32_t*)&p0;
    pk.y = *(uint32_t*)&p1;
    *(uint2*)(dst + e) = pk;
}

// ---------------- attention logits: one warp per (b, n) ----------------
__global__ void __launch_bounds__(256) k_att(const float* __restrict__ feat,
        const float* __restrict__ Wv, const float* __restrict__ bv) {
    int warp = threadIdx.x >> 5, lane = threadIdx.x & 31;
    int b = blockIdx.y;
    int n = blockIdx.x * 8 + warp;
    if (n >= VNUM) return;
    const float* fr = feat + ((size_t)b * VNUM + n) * VDIM;
    float acc = 0.f;
    #pragma unroll
    for (int k = lane; k < VDIM; k += 32) acc += fr[k] * Wv[k];
    #pragma unroll
    for (int o = 16; o; o >>= 1) acc += __shfl_xor_sync(0xffffffffu, acc, o);
    if (lane == 0) d_attv[b * VNUM + n] = acc + bv[0];
}

// ---------------- softmax(attv) -> feat_sum + ctx ----------------
__global__ void __launch_bounds__(256) k_ctx(const float* __restrict__ feat) {
    __shared__ float salpha[VNUM];
    __shared__ float red[256];
    __shared__ float sfs[256];
    __shared__ float sctx[256];
    int b = blockIdx.y, tid = threadIdx.x;
    int v0 = blockIdx.x * 128;
    float x = (tid < VNUM) ? d_attv[b * VNUM + tid] : -1e30f;
    red[tid] = x; __syncthreads();
    for (int s = 128; s; s >>= 1) { if (tid < s) red[tid] = fmaxf(red[tid], red[tid + s]); __syncthreads(); }
    float mx = red[0]; __syncthreads();
    float e = (tid < VNUM) ? __expf(x - mx) : 0.f;
    red[tid] = e; __syncthreads();
    for (int s = 128; s; s >>= 1) { if (tid < s) red[tid] += red[tid + s]; __syncthreads(); }
    float inv = 1.f / red[0];
    __syncthreads();
    if (tid < VNUM) salpha[tid] = e * inv;
    __syncthreads();

    int v = v0 + (tid & 127);
    int half = tid >> 7;
    int n0 = half * 98, n1 = n0 + 98;
    if (n1 > VNUM) n1 = VNUM;
    const float* fp = feat + (size_t)b * VNUM * VDIM + v;
    float fs = 0.f, c0 = 0.f, c1 = 0.f, c2 = 0.f, c3 = 0.f;
    int n = n0;
    for (; n + 4 <= n1; n += 4) {
        float x0 = fp[(size_t)n * VDIM];
        float x1 = fp[(size_t)(n + 1) * VDIM];
        float x2 = fp[(size_t)(n + 2) * VDIM];
        float x3 = fp[(size_t)(n + 3) * VDIM];
        fs += (x0 + x1) + (x2 + x3);
        c0 += salpha[n] * x0; c1 += salpha[n + 1] * x1;
        c2 += salpha[n + 2] * x2; c3 += salpha[n + 3] * x3;
    }
    for (; n < n1; n++) { float xx = fp[(size_t)n * VDIM]; fs += xx; c0 += salpha[n] * xx; }
    sfs[tid] = fs;
    sctx[tid] = (c0 + c1) + (c2 + c3);
    __syncthreads();
    if (half == 0) {
        d_feat_sum[b * VDIM + v] = sfs[tid] + sfs[tid + 128];
        d_ctx[b * VDIM + v] = sctx[tid] + sctx[tid + 128];
    }
}

// ---------------- fused init GEMMs: h0(bf16) | c0 | g_ctx (N=3072 concat) ----------------
__global__ void __launch_bounds__(256) k_init(
        const float* __restrict__ Wini_h, const float* __restrict__ Wini_c,
        const float* __restrict__ Wih,
        const float* __restrict__ bih, const float* __restrict__ bhh) {
    __shared__ float As[16][32];
    __shared__ float Bs[16][64];
    int ntile = blockIdx.x, mt = blockIdx.y;
    int seg, nloc0;
    const float* A;
    const float* B;
    int ldb;
    if (ntile < 8)       { seg = 0; nloc0 = ntile * 64;        A = d_feat_sum; B = Wini_h; ldb = VDIM; }
    else if (ntile < 16) { seg = 1; nloc0 = (ntile - 8) * 64;  A = d_feat_sum; B = Wini_c; ldb = VDIM; }
    else                 { seg = 2; nloc0 = (ntile - 16) * 64; A = d_ctx;      B = Wih;    ldb = VDIM + NE; }
    int tid = threadIdx.x;
    int tx = tid & 15, ty = tid >> 4;
    int m0 = mt * 32;
    float acc[2][4] = {{0.f, 0.f, 0.f, 0.f}, {0.f, 0.f, 0.f, 0.f}};
    for (int k0 = 0; k0 < VDIM; k0 += 16) {
        {
            int i = tid; int r = i >> 4, kk = i & 15;
            As[kk][r] = A[(size_t)(m0 + r) * VDIM + k0 + kk];
            i = tid + 256; r = i >> 4; kk = i & 15;
            As[kk][r] = A[(size_t)(m0 + r) * VDIM + k0 + kk];
        }
        #pragma unroll
        for (int j = 0; j < 4; j++) {
            int i = tid + j * 256; int r = i >> 4, kk = i & 15;
            Bs[kk][r] = B[(size_t)(nloc0 + r) * ldb + k0 + kk];
        }
        __syncthreads();
        #pragma unroll
        for (int kk = 0; kk < 16; kk++) {
            float a0 = As[kk][ty * 2], a1 = As[kk][ty * 2 + 1];
            float b0 = Bs[kk][tx * 4], b1 = Bs[kk][tx * 4 + 1];
            float b2 = Bs[kk][tx * 4 + 2], b3 = Bs[kk][tx * 4 + 3];
            acc[0][0] += a0 * b0; acc[0][1] += a0 * b1; acc[0][2] += a0 * b2; acc[0][3] += a0 * b3;
            acc[1][0] += a1 * b0; acc[1][1] += a1 * b1; acc[1][2] += a1 * b2; acc[1][3] += a1 * b3;
        }
        __syncthreads();
    }
    #pragma unroll
    for (int i = 0; i < 2; i++) {
        int m = m0 + ty * 2 + i;
        #pragma unroll
        for (int j = 0; j < 4; j++) {
            int n = nloc0 + tx * 4 + j;
            if (seg == 0) {
                d_h0_bf[(size_t)m * NH + n] = __float2bfloat16(acc[i][j] * (1.f / VNUM));
            } else if (seg == 1) {
                d_c0[(size_t)m * NH + n] = acc[i][j] * (1.f / VNUM);
            } else {
                d_gctx[(size_t)m * G4 + n] = acc[i][j] + bih[n] + bhh[n];
            }
        }
    }
}

// ======================= bf16 mma GEMM: BK=64, 3-stage cp.async, 2 CTAs/SM =========
#define BSTR64 72
#define TB_BUF (128 * BSTR64)
#define TB_STAGE_BYTES (2 * TB_BUF * 2)
#define TB_SMEM (3 * TB_STAGE_BYTES)

__global__ void __launch_bounds__(256, 2) tbmma(const __nv_bfloat16* __restrict__ A, int lda,
        const __nv_bfloat16* __restrict__ B, int ldb,
        float* __restrict__ C, __nv_bfloat16* __restrict__ Cb,
        int M, int N, int K,
        const float* __restrict__ bias, const float* __restrict__ addM, int addRowMod) {
    extern __shared__ __align__(16) __nv_bfloat16 smb[];
    int tid = threadIdx.x, lane = tid & 31, wid = tid >> 5;
    int wm = wid & 1, wn = wid >> 1;
    int m0 = blockIdx.y * 128, n0 = blockIdx.x * 128;
    int gid = lane >> 2, tig = lane & 3;

    float acc[4][4][4];
    #pragma unroll
    for (int mi = 0; mi < 4; mi++)
        #pragma unroll
        for (int ni = 0; ni < 4; ni++)
            #pragma unroll
            for (int q = 0; q < 4; q++) acc[mi][ni][q] = 0.f;

    int rr[4], ss[4];
    #pragma unroll
    for (int j = 0; j < 4; j++) { int idx = tid + j * 256; rr[j] = idx >> 3; ss[j] = idx & 7; }
    uint32_t sm0 = smem_u32(smb);

    int iters = K >> 6;
    int lrow = lane & 15;
    int lcg = (lane >> 4) << 3;

    #define STAGE(ck, bsel) do {                                                          \
        int k0_ = (ck) << 6;                                                              \
        uint32_t da = sm0 + (bsel) * TB_STAGE_BYTES;                                      \
        uint32_t db = da + TB_BUF * 2;                                                    \
        _Pragma("unroll")                                                                 \
        for (int j = 0; j < 4; j++)                                                       \
            cpa16(da + (rr[j] * BSTR64 + ss[j] * 8) * 2,                                  \
                  A + (size_t)(m0 + rr[j]) * lda + k0_ + ss[j] * 8, 16u);                 \
        _Pragma("unroll")                                                                 \
        for (int j = 0; j < 4; j++) {                                                     \
            int n = n0 + rr[j];                                                           \
            uint32_t sz = (n < N) ? 16u : 0u;                                             \
            cpa16(db + (rr[j] * BSTR64 + ss[j] * 8) * 2,                                  \
                  B + (size_t)(n < N ? n : 0) * ldb + k0_ + ss[j] * 8, sz);               \
        }                                                                                 \
        CP_COMMIT();                                                                      \
    } while (0)

    STAGE(0, 0);
    STAGE(1, 1);

    int bc = 0;
    for (int it = 0; it < iters; it++) {
        CP_WAIT1();
        __syncthreads();
        int bs = bc + 2; if (bs >= 3) bs -= 3;
        if (it + 2 < iters) STAGE(it + 2, bs);
        uint32_t ab = sm0 + bc * TB_STAGE_BYTES;
        uint32_t bb = ab + TB_BUF * 2;
        #pragma unroll
        for (int ks = 0; ks < 4; ks++) {
            int kofs = ks * 16 + lcg;
            uint32_t a[4][4], b[4][2];
            #pragma unroll
            for (int mi = 0; mi < 4; mi++)
                ldsm4(a[mi], ab + ((wm * 64 + mi * 16 + lrow) * BSTR64 + kofs) * 2);
            #pragma unroll
            for (int np = 0; np < 2; np++) {
                uint32_t r[4];
                ldsm4(r, bb + ((wn * 32 + np * 16 + lrow) * BSTR64 + kofs) * 2);
                b[2 * np][0] = r[0]; b[2 * np + 1][0] = r[1];
                b[2 * np][1] = r[2]; b[2 * np + 1][1] = r[3];
            }
            #pragma unroll
            for (int mi = 0; mi < 4; mi++)
                #pragma unroll
                for (int ni = 0; ni < 4; ni++)
                    mma16(acc[mi][ni], a[mi], b[ni]);
        }
        bc++; if (bc == 3) bc = 0;
    }

    #pragma unroll
    for (int mi = 0; mi < 4; mi++) {
        int row0 = m0 + wm * 64 + mi * 16 + gid;
        #pragma unroll
        for (int ni = 0; ni < 4; ni++) {
            int col = n0 + wn * 32 + ni * 8 + tig * 2;
            #pragma unroll
            for (int half = 0; half < 2; half++) {
                int r = row0 + half * 8;
                float v0 = acc[mi][ni][half * 2 + 0];
                float v1 = acc[mi][ni][half * 2 + 1];
                if (bias) { v0 += bias[col]; v1 += (col + 1 < N) ? bias[col + 1] : 0.f; }
                if (addM) {
                    int ar = r % addRowMod;
                    v0 += addM[(size_t)ar * N + col];
                    if (col + 1 < N) v1 += addM[(size_t)ar * N + col + 1];
                }
                if (C) {
                    if (col < N)     C[(size_t)r * N + col]     = v0;
                    if (col + 1 < N) C[(size_t)r * N + col + 1] = v1;
                } else {
                    if (col + 1 < N) {
                        __nv_bfloat162 p = __floats2bfloat162_rn(v0, v1);
                        *(uint32_t*)(Cb + (size_t)r * NV + col) = *(uint32_t*)&p;
                    } else if (col < N) {
                        Cb[(size_t)r * NV + col] = __float2bfloat16(v0);
                    }
                }
            }
        }
    }
    #undef STAGE
}

// ======================= persistent recurrence (bf16 mma + ldmatrix) ==========
// Per-mt group barrier: only the 32 blocks sharing an mt (same 32 batch rows)
// need to synchronize each step.
__device__ __forceinline__ void group_barrier(int g) {
    __syncthreads();
    if (threadIdx.x == 0) {
        unsigned gen = *((volatile unsigned*)&d_barGen4[g]);
        __threadfence();
        if (atomicAdd(&d_barCount4[g], 1u) == 31u) {
            d_barCount4[g] = 0u;
            __threadfence();
            atomicAdd(&d_barGen4[g], 1u);
        } else {
            while (*((volatile unsigned*)&d_barGen4[g]) == gen) {}
        }
        __threadfence();
    }
    __syncthreads();
}

#define RSTR2 520
#define RS_SMEM2 ((64 + 32) * RSTR2 * 2)

__global__ void __launch_bounds__(256, 1) k_recur(const float* __restrict__ Whh) {
    extern __shared__ __nv_bfloat16 rs[];
    __nv_bfloat16* Bs = rs;
    __nv_bfloat16* As = rs + 64 * RSTR2;
    int bid = blockIdx.x, tid = threadIdx.x;
    int mt = bid >> 5, nt = bid & 31;
    int lane = tid & 31, wid = tid >> 5;
    int wm = wid & 1, wn = wid >> 1;
    int gid = lane >> 2, tig = lane & 3;
    int lrow = lane & 15;
    int lcg = (lane >> 4) << 3;

    for (int i = tid; i < 64 * 128; i += 256) {
        int r = i >> 7, q = (i & 127) << 2;
        int w = ((r & 3) << 9) + (nt << 4) + (r >> 2);
        float4 v = *(const float4*)(Whh + (size_t)w * NH + q);
        __nv_bfloat162 p0 = __floats2bfloat162_rn(v.x, v.y);
        __nv_bfloat162 p1 = __floats2bfloat162_rn(v.z, v.w);
        uint2 pk; pk.x = *(uint32_t*)&p0; pk.y = *(uint32_t*)&p1;
        *(uint2*)(Bs + r * RSTR2 + q) = pk;
    }

    int mrow0 = mt * 32 + wm * 16 + gid;
    int g0 = (2 * tig) & 3, g1 = (2 * tig + 1) & 3;
    float creg[2][2];
    int jcol[2], gp0_[2], gp1_[2];
    #pragma unroll
    for (int ni = 0; ni < 2; ni++) {
        int jj = wn * 4 + ni * 2 + (tig >> 1);
        int j = nt * 16 + jj;
        jcol[ni] = j;
        gp0_[ni] = g0 * 512 + j;
        gp1_[ni] = g1 * 512 + j;
        creg[ni][0] = d_c0[mrow0 * NH + j];
        creg[ni][1] = d_c0[(mrow0 + 8) * NH + j];
    }

    uint32_t sB0 = smem_u32(Bs), sA0 = smem_u32(As);
    uint32_t aAddr = sA0 + ((wm * 16 + lrow) * RSTR2 + lcg) * 2;
    uint32_t bAddr = sB0 + ((wn * 16 + lrow) * RSTR2 + lcg) * 2;

    for (int t = 0; t < NT; t++) {
        const __nv_bfloat16* hsrc = (t == 0) ? d_h0_bf : (d_hall_bf + (size_t)(t - 1) * NB * NH);
        for (int i = tid; i < 32 * 64; i += 256) {
            int r = i >> 6, q = (i & 63) << 3;
            *(uint4*)(As + r * RSTR2 + q) = *(const uint4*)(hsrc + (size_t)(mt * 32 + r) * NH + q);
        }
        __syncthreads();

        float acc[2][4] = {{0.f, 0.f, 0.f, 0.f}, {0.f, 0.f, 0.f, 0.f}};
        #pragma unroll 8
        for (int kc = 0; kc < 512; kc += 16) {
            uint32_t a[4], r[4];
            ldsm4(a, aAddr + kc * 2);
            ldsm4(r, bAddr + kc * 2);
            uint32_t b0[2] = { r[0], r[2] };
            uint32_t b1[2] = { r[1], r[3] };
            mma16(acc[0], a, b0);
            mma16(acc[1], a, b1);
        }

        const float* gp = d_gpre + (size_t)t * NB * G4;
        __nv_bfloat16* hb = d_hall_bf + (size_t)t * NB * NH;
        #pragma unroll
        for (int ni = 0; ni < 2; ni++) {
            float v0 = acc[ni][0] + gp[(size_t)mrow0 * G4 + gp0_[ni]];
            float v1 = acc[ni][1] + gp[(size_t)mrow0 * G4 + gp1_[ni]];
            float v2 = acc[ni][2] + gp[(size_t)(mrow0 + 8) * G4 + gp0_[ni]];
            float v3 = acc[ni][3] + gp[(size_t)(mrow0 + 8) * G4 + gp1_[ni]];
            float w0 = __shfl_xor_sync(0xffffffffu, v0, 1);
            float w1 = __shfl_xor_sync(0xffffffffu, v1, 1);
            float w2 = __shfl_xor_sync(0xffffffffu, v2, 1);
            float w3 = __shfl_xor_sync(0xffffffffu, v3, 1);
            float iA, fA, gA, oA, iB, fB, gB, oB;
            if ((tig & 1) == 0) { iA = v0; fA = v1; gA = w0; oA = w1; iB = v2; fB = v3; gB = w2; oB = w3; }
            else                { iA = w0; fA = w1; gA = v0; oA = v1; iB = w2; fB = w3; gB = v2; oB = v3; }
            float c0n = sigmoidf_(fA) * creg[ni][0] + sigmoidf_(iA) * tanhf(gA);
            float h0v = sigmoidf_(oA) * tanhf(c0n);
            creg[ni][0] = c0n;
            float c1n = sigmoidf_(fB) * creg[ni][1] + sigmoidf_(iB) * tanhf(gB);
            float h1v = sigmoidf_(oB) * tanhf(c1n);
            creg[ni][1] = c1n;
            if ((tig & 1) == 0) {
                hb[(size_t)mrow0 * NH + jcol[ni]] = __float2bfloat16(h0v);
                hb[(size_t)(mrow0 + 8) * NH + jcol[ni]] = __float2bfloat16(h1v);
            }
        }
        group_barrier(mt);
    }
}

// ======================= output softmax (bf16 logits in, fp32 out) ====================
#define NV8 1250   // NV / 8

__global__ void __launch_bounds__(512) k_out(float* __restrict__ out) {
    __shared__ __align__(16) float row[NV];
    __shared__ float red[512];
    int r = blockIdx.x, tid = threadIdx.x;
    const uint4* L = (const uint4*)(d_logits_bf + (size_t)r * NV);
    float mx = -1e30f;
    for (int v = tid; v < NV8; v += 512) {
        uint4 u = L[v];
        float2 f0 = __bfloat1622float2(*(__nv_bfloat162*)&u.x);
        float2 f1 = __bfloat1622float2(*(__nv_bfloat162*)&u.y);
        float2 f2 = __bfloat1622float2(*(__nv_bfloat162*)&u.z);
        float2 f3 = __bfloat1622float2(*(__nv_bfloat162*)&u.w);
        float4 a = make_float4(f0.x, f0.y, f1.x, f1.y);
        float4 b = make_float4(f2.x, f2.y, f3.x, f3.y);
        *(float4*)(row + v * 8) = a;
        *(float4*)(row + v * 8 + 4) = b;
        mx = fmaxf(mx, fmaxf(fmaxf(a.x, a.y), fmaxf(a.z, a.w)));
        mx = fmaxf(mx, fmaxf(fmaxf(b.x, b.y), fmaxf(b.z, b.w)));
    }
    red[tid] = mx; __syncthreads();
    for (int s = 256; s; s >>= 1) { if (tid < s) red[tid] = fmaxf(red[tid], red[tid + s]); __syncthreads(); }
    mx = red[0]; __syncthreads();
    float sum = 0.f;
    for (int v = tid; v < NV / 4; v += 512) {
        float4 x = *(const float4*)(row + v * 4);
        sum += (__expf(x.x - mx) + __expf(x.y - mx)) + (__expf(x.z - mx) + __expf(x.w - mx));
    }
    red[tid] = sum; __syncthreads();
    for (int s = 256; s; s >>= 1) { if (tid < s) red[tid] += red[tid + s]; __syncthreads(); }
    float sh = mx + logf(red[0]);
    float4* o1 = (float4*)(out + (size_t)r * NV);
    float4* o2 = (float4*)(out + (size_t)TBR * NV + (size_t)r * NV);
    for (int v = tid; v < NV / 4; v += 512) {
        float4 x = *(const float4*)(row + v * 4);
        float4 lp, p;
        lp.x = x.x - sh; lp.y = x.y - sh; lp.z = x.z - sh; lp.w = x.w - sh;
        p.x = __expf(lp.x); p.y = __expf(lp.y); p.z = __expf(lp.z); p.w = __expf(lp.w);
        o1[v] = lp;
        o2[v] = p;
    }
}

// ======================= launch =======================
extern "C" void kernel_launch(void* const* d_in, const int* in_sizes, int n_in,
                              void* d_out, int out_size) {
    const float* features = (const float*)d_in[0];
    const int*   captions = (const int*)d_in[1];
    const float* W_init_h = (const float*)d_in[2];
    const float* W_init_c = (const float*)d_in[3];
    const float* Wv       = (const float*)d_in[4];
    const float* bv       = (const float*)d_in[5];
    // d_in[6]=Wa, d_in[7]=ba unused (softmax shift-invariance)
    const float* embed    = (const float*)d_in[8];
    const float* W_ih     = (const float*)d_in[9];
    const float* W_hh     = (const float*)d_in[10];
    const float* b_ih     = (const float*)d_in[11];
    const float* b_hh     = (const float*)d_in[12];
    const float* Wo       = (const float*)d_in[13];
    const float* bo       = (const float*)d_in[14];
    float* out = (float*)d_out;

    float *p_gctx, *p_gpre;
    __nv_bfloat16 *p_ebf, *p_wobf, *p_wibf, *p_hbf, *p_lbf;
    cudaGetSymbolAddress((void**)&p_gctx,   d_gctx);
    cudaGetSymbolAddress((void**)&p_gpre,   d_gpre);
    cudaGetSymbolAddress((void**)&p_ebf,    d_emb_bf);
    cudaGetSymbolAddress((void**)&p_wobf,   d_wo_bf);
    cudaGetSymbolAddress((void**)&p_wibf,   d_wih_bf);
    cudaGetSymbolAddress((void**)&p_hbf,    d_hall_bf);
    cudaGetSymbolAddress((void**)&p_lbf,    d_logits_bf);

    static int smset = 0;
    if (!smset) {
        cudaFuncSetAttribute(k_recur, cudaFuncAttributeMaxDynamicSharedMemorySize, RS_SMEM2);
        cudaFuncSetAttribute(tbmma, cudaFuncAttributeMaxDynamicSharedMemorySize, TB_SMEM);
        smset = 1;
    }

    // setup + conversions
    k_gather<<<TBR, NE>>>(captions, embed);
    k_cvtb<<<(NV * NH / 4 + 255) / 256, 256>>>(Wo, NH, NH, p_wobf, NV * NH / 4);
    k_cvtb<<<(G4 * NE / 4 + 255) / 256, 256>>>(W_ih + VDIM, VDIM + NE, NE, p_wibf, G4 * NE / 4);

    // visual stage
    k_att<<<dim3(25, NB), 256>>>(features, Wv, bv);
    k_ctx<<<dim3(4, NB), 256>>>(features);

    // fused h0 | c0 | g_ctx
    k_init<<<dim3(48, 4), 256>>>(W_init_h, W_init_c, W_ih, b_ih, b_hh);

    // g_pre = emb @ WihE^T + g_ctx[b]  (bf16 mma, fp32 out)
    tbmma<<<dim3(G4 / 128, TBR / 128), 256, TB_SMEM>>>(
        p_ebf, NE, p_wibf, NE, p_gpre, nullptr, TBR, G4, NE, nullptr, p_gctx, NB);

    // recurrence (bf16 mma + ldmatrix, per-mt group barrier each step)
    k_recur<<<NB, 256, RS_SMEM2>>>(W_hh);

    // logits = hall @ Wo^T + bo  (bf16 mma, bf16 out)
    tbmma<<<dim3((NV + 127) / 128, TBR / 128), 256, TB_SMEM>>>(
        p_hbf, NH, p_wobf, NH, nullptr, p_lbf, TBR, NV, NH, bo, nullptr, 0);

    k_out<<<TBR, 512>>>(out);
}